// round 7
// baseline (speedup 1.0000x reference)
#include <cuda_runtime.h>
#include <math.h>

// Problem shape (fixed by the reference)
#define BB   32
#define CC   256
#define HH   128
#define WW   128
#define HWSZ (HH * WW)       // 16384
#define HW4  (HWSZ / 4)      // 4096 float4 per (b) spatial plane

// Scratch (allocation-free: __device__ globals). 3 * 2 MiB, L2-resident.
__device__ float g_avg[BB * HWSZ];
__device__ float g_max[BB * HWSZ];
__device__ float g_gate[BB * HWSZ];

// ---------------------------------------------------------------------------
// Kernel 1: channel-wise mean + max of y.  y: [B, C, H, W] fp32.
// R4-proven config: 512 CTAs, thread owns one float4 column, unroll 8.
// Measured: 79.2 us @ 86.3% DRAM (6.84 TB/s) — at the practical read ceiling.
// ---------------------------------------------------------------------------
__global__ __launch_bounds__(256) void reduce_bc(const float* __restrict__ y) {
    const int b = blockIdx.y;
    const int t = blockIdx.x * blockDim.x + threadIdx.x;   // 0 .. HW4-1

    const float4* yp = reinterpret_cast<const float4*>(y)
                     + (size_t)b * CC * HW4 + t;

    float4 s = make_float4(0.f, 0.f, 0.f, 0.f);
    float4 m = make_float4(-INFINITY, -INFINITY, -INFINITY, -INFINITY);

    #pragma unroll 8
    for (int c = 0; c < CC; ++c) {
        float4 v = yp[(size_t)c * HW4];
        s.x += v.x; s.y += v.y; s.z += v.z; s.w += v.w;
        m.x = fmaxf(m.x, v.x); m.y = fmaxf(m.y, v.y);
        m.z = fmaxf(m.z, v.z); m.w = fmaxf(m.w, v.w);
    }

    const float inv = 1.0f / (float)CC;
    float4 a = make_float4(s.x * inv, s.y * inv, s.z * inv, s.w * inv);

    reinterpret_cast<float4*>(g_avg)[(size_t)b * HW4 + t] = a;
    reinterpret_cast<float4*>(g_max)[(size_t)b * HW4 + t] = m;
}

// ---------------------------------------------------------------------------
// Kernel 2: 3x3 conv over the 2-channel [avg; max] map, zero padding,
// then sigmoid -> gate[B, H, W]. Inputs L2-resident (4 MiB). R4-proven.
// conv_w layout [1,2,3,3] row-major; NCHW/OIHW conv = correlation (no flip).
// ---------------------------------------------------------------------------
__global__ __launch_bounds__(256) void conv_gate(const float* __restrict__ cw) {
    const int idx = blockIdx.x * blockDim.x + threadIdx.x;
    if (idx >= BB * HWSZ) return;

    const int b  = idx >> 14;          // / HWSZ
    const int hw = idx & (HWSZ - 1);
    const int h  = hw >> 7;            // / WW
    const int w  = hw & (WW - 1);

    float wt[18];
    #pragma unroll
    for (int i = 0; i < 18; ++i) wt[i] = __ldg(&cw[i]);

    float acc = 0.0f;
    #pragma unroll
    for (int di = -1; di <= 1; ++di) {
        const int hh = h + di;
        if (hh < 0 || hh >= HH) continue;
        #pragma unroll
        for (int dj = -1; dj <= 1; ++dj) {
            const int ww2 = w + dj;
            if (ww2 < 0 || ww2 >= WW) continue;
            const int off = b * HWSZ + hh * WW + ww2;
            const int k   = (di + 1) * 3 + (dj + 1);
            acc = fmaf(g_avg[off], wt[k],     acc);
            acc = fmaf(g_max[off], wt[9 + k], acc);
        }
    }
    g_gate[idx] = 1.0f / (1.0f + expf(-acc));
}

// ---------------------------------------------------------------------------
// Kernel 3: out = x * gate (gate broadcast over C), BURST-BATCHED.
// Per macro-iteration: 8 back-to-back LDG.128 (1 KiB read burst per thread)
// into a register buffer, then 8 back-to-back STG.128 (1 KiB write burst).
// Longer same-direction DRAM bursts cut read<->write turnaround loss.
// __launch_bounds__(256,4): regs <= 64 so 512 CTAs stay one wave (4 CTA/SM).
// ---------------------------------------------------------------------------
__global__ __launch_bounds__(256, 4) void apply_gate(const float* __restrict__ x,
                                                      float* __restrict__ out) {
    const int b  = blockIdx.y;
    const int t4 = blockIdx.x * 256 + threadIdx.x;   // float4 index in plane

    const float4 g = reinterpret_cast<const float4*>(g_gate)[(size_t)b * HW4 + t4];

    const size_t base = (size_t)b * CC * HW4 + t4;
    const float4* xp = reinterpret_cast<const float4*>(x) + base;
    float4*       op = reinterpret_cast<float4*>(out)     + base;

    #pragma unroll 1
    for (int cb = 0; cb < CC / 8; ++cb) {            // 32 macro-iterations
        const size_t o0 = (size_t)(cb * 8) * HW4;
        float4 v[8];
        #pragma unroll
        for (int u = 0; u < 8; ++u)
            v[u] = xp[o0 + (size_t)u * HW4];         // 8x LDG.128 burst
        #pragma unroll
        for (int u = 0; u < 8; ++u) {
            v[u].x *= g.x; v[u].y *= g.y; v[u].z *= g.z; v[u].w *= g.w;
        }
        #pragma unroll
        for (int u = 0; u < 8; ++u)
            op[o0 + (size_t)u * HW4] = v[u];         // 8x STG.128 burst
    }
}

// ---------------------------------------------------------------------------
// Launch. Inputs (metadata order): d_in[0]=x [B,C,H,W] f32,
// d_in[1]=y [B,C,H,W] f32, d_in[2]=conv_w [1,2,3,3] f32. Output f32 [B,C,H,W].
// ---------------------------------------------------------------------------
extern "C" void kernel_launch(void* const* d_in, const int* in_sizes, int n_in,
                              void* d_out, int out_size) {
    (void)in_sizes; (void)n_in; (void)out_size;
    const float* x  = (const float*)d_in[0];
    const float* y  = (const float*)d_in[1];
    const float* cw = (const float*)d_in[2];
    float* out = (float*)d_out;

    dim3 grid(HW4 / 256, BB);            // (16, 32) = 512 CTAs
    reduce_bc<<<grid, 256>>>(y);

    conv_gate<<<(BB * HWSZ + 255) / 256, 256>>>(cw);

    apply_gate<<<grid, 256>>>(x, out);
}

// round 8
// speedup vs baseline: 1.0382x; 1.0382x over previous
#include <cuda_runtime.h>
#include <math.h>

// Problem shape (fixed by the reference)
#define BB   32
#define CC   256
#define HH   128
#define WW   128
#define HWSZ (HH * WW)       // 16384
#define HW4  (HWSZ / 4)      // 4096 float4 per (b) spatial plane

// Scratch (allocation-free: __device__ globals). 2 * 2 MiB, L2-resident.
__device__ float g_avg[BB * HWSZ];
__device__ float g_max[BB * HWSZ];

// ---------------------------------------------------------------------------
// Kernel 1: channel-wise mean + max of y.  y: [B, C, H, W] fp32.
// R4-proven config: 512 CTAs, thread owns one float4 column, unroll 8.
// Measured: 79.2 us @ 86.3% DRAM (6.84 TB/s) — practical read ceiling.
// ---------------------------------------------------------------------------
__global__ __launch_bounds__(256) void reduce_bc(const float* __restrict__ y) {
    const int b = blockIdx.y;
    const int t = blockIdx.x * blockDim.x + threadIdx.x;   // 0 .. HW4-1

    const float4* yp = reinterpret_cast<const float4*>(y)
                     + (size_t)b * CC * HW4 + t;

    float4 s = make_float4(0.f, 0.f, 0.f, 0.f);
    float4 m = make_float4(-INFINITY, -INFINITY, -INFINITY, -INFINITY);

    #pragma unroll 8
    for (int c = 0; c < CC; ++c) {
        float4 v = yp[(size_t)c * HW4];
        s.x += v.x; s.y += v.y; s.z += v.z; s.w += v.w;
        m.x = fmaxf(m.x, v.x); m.y = fmaxf(m.y, v.y);
        m.z = fmaxf(m.z, v.z); m.w = fmaxf(m.w, v.w);
    }

    const float inv = 1.0f / (float)CC;
    float4 a = make_float4(s.x * inv, s.y * inv, s.z * inv, s.w * inv);

    reinterpret_cast<float4*>(g_avg)[(size_t)b * HW4 + t] = a;
    reinterpret_cast<float4*>(g_max)[(size_t)b * HW4 + t] = m;
}

// ---------------------------------------------------------------------------
// Kernel 2 (fused conv + apply) — R6-proven fusion (conv prologue measured
// free: 175.4us fused == standalone apply), now with unroll-4 main loop to
// cut oe*MLP_p1 below the cross-CTA L1tex-queue spread threshold.
//
// Prologue: per thread, gate for its 4 same-row pixels via 3x3x2 correlation
//   (zero pad) + sigmoid, from L2-resident g_avg/g_max (4 MiB).
//   conv_w [1,2,3,3] row-major; NCHW/OIHW conv = correlation (no flip).
// Main loop: out = x * gate over 256 channels, gate in registers.
// ---------------------------------------------------------------------------
__global__ __launch_bounds__(256) void conv_apply(const float* __restrict__ x,
                                                  const float* __restrict__ cw,
                                                  float* __restrict__ out) {
    const int b  = blockIdx.y;
    const int t4 = blockIdx.x * 256 + threadIdx.x;   // float4 index in plane
    const int p0 = t4 * 4;                           // first pixel index
    const int h  = p0 >> 7;                          // row (4 px share a row)
    const int w0 = p0 & (WW - 1);                    // first col (0..124)

    // ---- gate prologue -------------------------------------------------
    float wt[18];
    #pragma unroll
    for (int i = 0; i < 18; ++i) wt[i] = __ldg(&cw[i]);

    // 3 rows x 6 cols neighborhood (zero-padded) for 4 output pixels
    float A[3][6], M[3][6];
    #pragma unroll
    for (int r = 0; r < 3; ++r) {
        const int hh = h - 1 + r;
        const bool hv = (hh >= 0) && (hh < HH);
        #pragma unroll
        for (int cc = 0; cc < 6; ++cc) {
            const int ww = w0 - 1 + cc;
            const bool v = hv && (ww >= 0) && (ww < WW);
            const int off = b * HWSZ + hh * WW + ww;
            A[r][cc] = v ? __ldg(&g_avg[off]) : 0.0f;
            M[r][cc] = v ? __ldg(&g_max[off]) : 0.0f;
        }
    }

    float4 g;
    float* gp = &g.x;
    #pragma unroll
    for (int i = 0; i < 4; ++i) {
        float acc = 0.0f;
        #pragma unroll
        for (int r = 0; r < 3; ++r) {
            #pragma unroll
            for (int dj = 0; dj < 3; ++dj) {
                const int k = r * 3 + dj;
                acc = fmaf(A[r][i + dj], wt[k],     acc);
                acc = fmaf(M[r][i + dj], wt[9 + k], acc);
            }
        }
        gp[i] = 1.0f / (1.0f + expf(-acc));
    }

    // ---- apply main loop (unroll 4: moderate MLP, low cross-CTA spread) --
    const size_t base = (size_t)b * CC * HW4 + t4;
    const float4* xp = reinterpret_cast<const float4*>(x) + base;
    float4*       op = reinterpret_cast<float4*>(out)     + base;

    #pragma unroll 4
    for (int c = 0; c < CC; ++c) {
        float4 v = xp[(size_t)c * HW4];
        v.x *= g.x; v.y *= g.y; v.z *= g.z; v.w *= g.w;
        op[(size_t)c * HW4] = v;
    }
}

// ---------------------------------------------------------------------------
// Launch. Inputs (metadata order): d_in[0]=x [B,C,H,W] f32,
// d_in[1]=y [B,C,H,W] f32, d_in[2]=conv_w [1,2,3,3] f32. Output f32 [B,C,H,W].
// ---------------------------------------------------------------------------
extern "C" void kernel_launch(void* const* d_in, const int* in_sizes, int n_in,
                              void* d_out, int out_size) {
    (void)in_sizes; (void)n_in; (void)out_size;
    const float* x  = (const float*)d_in[0];
    const float* y  = (const float*)d_in[1];
    const float* cw = (const float*)d_in[2];
    float* out = (float*)d_out;

    dim3 grid(HW4 / 256, BB);            // (16, 32) = 512 CTAs
    reduce_bc<<<grid, 256>>>(y);
    conv_apply<<<grid, 256>>>(x, cw, out);
}

// round 9
// speedup vs baseline: 1.0799x; 1.0401x over previous
#include <cuda_runtime.h>
#include <math.h>

// Problem shape (fixed by the reference)
#define BB   32
#define CC   256
#define HH   128
#define WW   128
#define HWSZ (HH * WW)       // 16384
#define HW4  (HWSZ / 4)      // 4096 float4 per (b) spatial plane
#define TPB  128             // 128-thread CTAs: 2x finer scheduling granularity

// Scratch (allocation-free: __device__ globals). 2 * 2 MiB, L2-resident.
__device__ float g_avg[BB * HWSZ];
__device__ float g_max[BB * HWSZ];

// ---------------------------------------------------------------------------
// Kernel 1: channel-wise mean + max of y.  y: [B, C, H, W] fp32.
// Per-thread work identical to the R4-proven config (one float4 column,
// unroll 8, 131072 threads). Only CTA granularity changed: 1024 x 128thr
// -> 6.92 CTAs/SM, tail imbalance 7-vs-6 instead of 4-vs-3.
// ---------------------------------------------------------------------------
__global__ __launch_bounds__(TPB, 8) void reduce_bc(const float* __restrict__ y) {
    const int b = blockIdx.y;
    const int t = blockIdx.x * TPB + threadIdx.x;   // 0 .. HW4-1

    const float4* yp = reinterpret_cast<const float4*>(y)
                     + (size_t)b * CC * HW4 + t;

    float4 s = make_float4(0.f, 0.f, 0.f, 0.f);
    float4 m = make_float4(-INFINITY, -INFINITY, -INFINITY, -INFINITY);

    #pragma unroll 8
    for (int c = 0; c < CC; ++c) {
        float4 v = yp[(size_t)c * HW4];
        s.x += v.x; s.y += v.y; s.z += v.z; s.w += v.w;
        m.x = fmaxf(m.x, v.x); m.y = fmaxf(m.y, v.y);
        m.z = fmaxf(m.z, v.z); m.w = fmaxf(m.w, v.w);
    }

    const float inv = 1.0f / (float)CC;
    float4 a = make_float4(s.x * inv, s.y * inv, s.z * inv, s.w * inv);

    reinterpret_cast<float4*>(g_avg)[(size_t)b * HW4 + t] = a;
    reinterpret_cast<float4*>(g_max)[(size_t)b * HW4 + t] = m;
}

// ---------------------------------------------------------------------------
// Kernel 2 (fused conv + apply) — R8-proven best (166.6us @ 78.2% DRAM):
// gate prologue from L2-resident g_avg/g_max, unroll-4 main loop.
// Only CTA granularity changed (128 threads, 1024 CTAs).
//
// Prologue: per thread, gate for its 4 same-row pixels via 3x3x2 correlation
//   (zero pad) + sigmoid. conv_w [1,2,3,3] row-major; NCHW/OIHW = correlation.
// Main loop: out = x * gate over 256 channels, gate in registers.
// ---------------------------------------------------------------------------
__global__ __launch_bounds__(TPB, 8) void conv_apply(const float* __restrict__ x,
                                                     const float* __restrict__ cw,
                                                     float* __restrict__ out) {
    const int b  = blockIdx.y;
    const int t4 = blockIdx.x * TPB + threadIdx.x;   // float4 index in plane
    const int p0 = t4 * 4;                           // first pixel index
    const int h  = p0 >> 7;                          // row (4 px share a row)
    const int w0 = p0 & (WW - 1);                    // first col (0..124)

    // ---- gate prologue -------------------------------------------------
    float wt[18];
    #pragma unroll
    for (int i = 0; i < 18; ++i) wt[i] = __ldg(&cw[i]);

    // 3 rows x 6 cols neighborhood (zero-padded) for 4 output pixels
    float A[3][6], M[3][6];
    #pragma unroll
    for (int r = 0; r < 3; ++r) {
        const int hh = h - 1 + r;
        const bool hv = (hh >= 0) && (hh < HH);
        #pragma unroll
        for (int cc = 0; cc < 6; ++cc) {
            const int ww = w0 - 1 + cc;
            const bool v = hv && (ww >= 0) && (ww < WW);
            const int off = b * HWSZ + hh * WW + ww;
            A[r][cc] = v ? __ldg(&g_avg[off]) : 0.0f;
            M[r][cc] = v ? __ldg(&g_max[off]) : 0.0f;
        }
    }

    float4 g;
    float* gp = &g.x;
    #pragma unroll
    for (int i = 0; i < 4; ++i) {
        float acc = 0.0f;
        #pragma unroll
        for (int r = 0; r < 3; ++r) {
            #pragma unroll
            for (int dj = 0; dj < 3; ++dj) {
                const int k = r * 3 + dj;
                acc = fmaf(A[r][i + dj], wt[k],     acc);
                acc = fmaf(M[r][i + dj], wt[9 + k], acc);
            }
        }
        gp[i] = 1.0f / (1.0f + expf(-acc));
    }

    // ---- apply main loop (unroll 4: proven best MLP for mixed R/W) ------
    const size_t base = (size_t)b * CC * HW4 + t4;
    const float4* xp = reinterpret_cast<const float4*>(x) + base;
    float4*       op = reinterpret_cast<float4*>(out)     + base;

    #pragma unroll 4
    for (int c = 0; c < CC; ++c) {
        float4 v = xp[(size_t)c * HW4];
        v.x *= g.x; v.y *= g.y; v.z *= g.z; v.w *= g.w;
        op[(size_t)c * HW4] = v;
    }
}

// ---------------------------------------------------------------------------
// Launch. Inputs (metadata order): d_in[0]=x [B,C,H,W] f32,
// d_in[1]=y [B,C,H,W] f32, d_in[2]=conv_w [1,2,3,3] f32. Output f32 [B,C,H,W].
// ---------------------------------------------------------------------------
extern "C" void kernel_launch(void* const* d_in, const int* in_sizes, int n_in,
                              void* d_out, int out_size) {
    (void)in_sizes; (void)n_in; (void)out_size;
    const float* x  = (const float*)d_in[0];
    const float* y  = (const float*)d_in[1];
    const float* cw = (const float*)d_in[2];
    float* out = (float*)d_out;

    dim3 grid(HW4 / TPB, BB);            // (32, 32) = 1024 CTAs of 128 thr
    reduce_bc<<<grid, TPB>>>(y);
    conv_apply<<<grid, TPB>>>(x, cw, out);
}